// round 10
// baseline (speedup 1.0000x reference)
#include <cuda_runtime.h>
#include <cstdint>

// Sparsemax along dim=-1 for X[4096, 32000] fp32. Persistent-CTA, rotated
// solve-ahead loop + TRUE double buffering (R9 fixed: per-buffer phase bits,
// R9's closed-form parity was wrong for buffer 0 -> deadlock):
//  - each row: first 24000 floats (96KB) via TMA ping-pong buffers (2x96KB),
//    last 8000 floats (32KB) via LDG issued right after the previous row's
//    stores free v[6..7] (latency hides under wait+copy).
//  - TMA(r+2) streams into the other buffer during ALL of iteration r ->
//    the DRAM read engine always has work outstanding.
//  - iter r: stores(r, tau known, .wb) -> LDG tail(r+1) -> wait buf(r+1)
//            -> copy+max -> re-issue TMA(r+3) -> solve tau(r+1)
//  - tau: support subset of {x > max-1} (~31 elems), ballot compaction +
//    warp0 Newton; block-register Newton fallback. NO __stcs (regressed 2x),
//    NO sub-row chunking (regressed 3x), NO L2 prefetch (regressed 2x).

#define NTHREADS 1024
#define D        32000
#define D4       8000
#define TMAF     24000         // floats per row via TMA
#define TMAB     96000u        // bytes per row via TMA
#define CSLOTS   64            // candidate slots per warp

__device__ __forceinline__ unsigned smem_u32(const void* p) {
    return (unsigned)__cvta_generic_to_shared(p);
}

__device__ __forceinline__ float warp_max_f(float v) {
    #pragma unroll
    for (int o = 16; o > 0; o >>= 1)
        v = fmaxf(v, __shfl_xor_sync(0xffffffffu, v, o));
    return v;
}

__device__ __forceinline__ void mbar_wait(unsigned mbar, unsigned ph) {
    asm volatile(
        "{\n\t"
        ".reg .pred P;\n\t"
        "WAIT_%=: \n\t"
        "mbarrier.try_wait.parity.acquire.cta.shared::cta.b64 P, [%0], %1, 0x989680;\n\t"
        "@P bra.uni DONE_%=;\n\t"
        "bra.uni WAIT_%=;\n\t"
        "DONE_%=: \n\t"
        "}\n\t" :: "r"(mbar), "r"(ph) : "memory");
}

__device__ __forceinline__ void tma_load(unsigned dst_smem, const float* src,
                                         unsigned mbar) {
    asm volatile("mbarrier.arrive.expect_tx.shared.b64 _, [%0], %1;"
                 :: "r"(mbar), "r"(TMAB) : "memory");
    asm volatile("cp.async.bulk.shared::cluster.global.mbarrier::complete_tx::bytes "
                 "[%0], [%1], %2, [%3];"
                 :: "r"(dst_smem), "l"(src), "r"(TMAB), "r"(mbar) : "memory");
}

__global__ void __launch_bounds__(NTHREADS, 1)
sparsemax_kernel(const float* __restrict__ X, float* __restrict__ Y, int nrows)
{
    __shared__ float s_warpf[32];
    __shared__ int   s_warpcnt[32];
    __shared__ float s_bcast;
    __shared__ float s_tau;
    __shared__ int   s_of;
    __shared__ __align__(8) unsigned long long s_mbar[2];

    extern __shared__ float s_dyn[];
    float* s_cand = s_dyn + 2 * TMAF;   // after the two TMA buffers

    const int t    = threadIdx.x;
    const int lane = t & 31;
    const int wid  = t >> 5;
    const int grid = gridDim.x;
    const int bid  = blockIdx.x;
    const float NINF = __int_as_float(0xff800000);

    if (t < 2)
        asm volatile("mbarrier.init.shared.b64 [%0], 1;"
                     :: "r"(smem_u32(&s_mbar[t])) : "memory");
    __syncthreads();

    if (bid >= nrows) return;
    const int nloc = (nrows - bid + grid - 1) / grid;   // local rows for this CTA
    const float4* __restrict__ X4 = reinterpret_cast<const float4*>(X);

    float4 v[8];
    #pragma unroll
    for (int i = 0; i < 8; i++) v[i] = make_float4(NINF, NINF, NINF, NINF);
    float vmax = NINF;
    float tau;
    unsigned phbits = 0;   // per-buffer expected parity; flip after each wait

    // ---- prologue: LDG row0 full (fused max); TMA rows 1 & 2 ---------------
    if (t < 1000) {
        const float4* src = X4 + (long long)bid * D4;
        #pragma unroll
        for (int i = 0; i < 8; i++) {
            v[i] = src[i * 1000 + t];
            vmax = fmaxf(vmax, fmaxf(fmaxf(v[i].x, v[i].y), fmaxf(v[i].z, v[i].w)));
        }
    }
    if (t == 0) {
        if (1 < nloc) tma_load(smem_u32(s_dyn + 1 * TMAF),
                               X + ((long long)bid + 1LL * grid) * D, smem_u32(&s_mbar[1]));
        if (2 < nloc) tma_load(smem_u32(s_dyn + 0 * TMAF),
                               X + ((long long)bid + 2LL * grid) * D, smem_u32(&s_mbar[0]));
    }

    // =====================  solve tau for the row in regs  ==================
    #define SOLVE_TAU()                                                        \
    do {                                                                       \
        float wm = warp_max_f(vmax);                                           \
        if (lane == 0) s_warpf[wid] = wm;                                      \
        if (t == 0) s_of = 0;                                                  \
        __syncthreads();                                                       \
        const float tau0 = warp_max_f(s_warpf[lane]) - 1.0f;                   \
        {                                                                      \
            int cnt = 0;                                                       \
            const unsigned lml = (1u << lane) - 1u;                            \
            const int base = wid * CSLOTS;                                     \
            _Pragma("unroll")                                                  \
            for (int i = 0; i < 8; i++) {                                      \
                float xs[4] = {v[i].x, v[i].y, v[i].z, v[i].w};                \
                _Pragma("unroll")                                              \
                for (int c = 0; c < 4; c++) {                                  \
                    float x = xs[c];                                           \
                    bool p = x > tau0;                                         \
                    unsigned m = __ballot_sync(0xffffffffu, p);                \
                    if (p) {                                                   \
                        int pos = cnt + __popc(m & lml);                       \
                        if (pos < CSLOTS) s_cand[base + pos] = x;              \
                    }                                                          \
                    cnt += __popc(m);                                          \
                }                                                              \
            }                                                                  \
            if (lane == 0) { s_warpcnt[wid] = cnt; if (cnt > CSLOTS) s_of = 1; } \
        }                                                                      \
        __syncthreads();                                                       \
        if (wid == 0) {                                                        \
            int n = s_warpcnt[lane]; if (n > CSLOTS) n = CSLOTS;               \
            const int base = lane * CSLOTS;                                    \
            float tt = tau0;                                                   \
            for (int it = 0; it < 64; it++) {                                  \
                float s = 0.0f; int k = 0;                                     \
                for (int j2 = 0; j2 < n; j2++) {                               \
                    float c = s_cand[base + j2];                               \
                    if (c > tt) { s += c; k++; }                               \
                }                                                              \
                _Pragma("unroll")                                              \
                for (int o = 16; o > 0; o >>= 1) {                             \
                    s += __shfl_xor_sync(0xffffffffu, s, o);                   \
                    k += __shfl_xor_sync(0xffffffffu, k, o);                   \
                }                                                              \
                float nt = (s - 1.0f) / (float)k;                              \
                if (nt == tt) break;                                           \
                tt = nt;                                                       \
            }                                                                  \
            if (lane == 0) s_tau = tt;                                         \
        }                                                                      \
        __syncthreads();                                                       \
        if (s_of) {                                                            \
            float tt = tau0;                                                   \
            for (int it = 0; it < 64; it++) {                                  \
                float s = 0.0f; int k = 0;                                     \
                _Pragma("unroll")                                              \
                for (int i = 0; i < 8; i++) {                                  \
                    if (v[i].x > tt) { s += v[i].x; k++; }                     \
                    if (v[i].y > tt) { s += v[i].y; k++; }                     \
                    if (v[i].z > tt) { s += v[i].z; k++; }                     \
                    if (v[i].w > tt) { s += v[i].w; k++; }                     \
                }                                                              \
                _Pragma("unroll")                                              \
                for (int o = 16; o > 0; o >>= 1) {                             \
                    s += __shfl_xor_sync(0xffffffffu, s, o);                   \
                    k += __shfl_xor_sync(0xffffffffu, k, o);                   \
                }                                                              \
                if (lane == 0) { s_warpf[wid] = s; s_warpcnt[wid] = k; }       \
                __syncthreads();                                               \
                if (t == 0) {                                                  \
                    float S = 0.0f; int K = 0;                                 \
                    _Pragma("unroll")                                          \
                    for (int w = 0; w < 32; w++) { S += s_warpf[w]; K += s_warpcnt[w]; } \
                    s_bcast = (S - 1.0f) / (float)K;                           \
                }                                                              \
                __syncthreads();                                               \
                float nt = s_bcast;                                            \
                if (nt == tt) break;                                           \
                tt = nt;                                                       \
            }                                                                  \
            if (t == 0) s_tau = tt;                                            \
            __syncthreads();                                                   \
        }                                                                      \
        tau = s_tau;                                                           \
    } while (0)

    SOLVE_TAU();   // tau(local row 0)

    for (int r = 0; ; r++) {
        const long long grow = bid + (long long)r * grid;

        // ---- 1) dense stores for row r (tau precomputed, .wb) --------------
        if (t < 1000) {
            float4* dst = reinterpret_cast<float4*>(Y) + grow * D4;
            #pragma unroll
            for (int i = 0; i < 8; i++) {
                float4 o;
                o.x = fmaxf(v[i].x - tau, 0.0f);
                o.y = fmaxf(v[i].y - tau, 0.0f);
                o.z = fmaxf(v[i].z - tau, 0.0f);
                o.w = fmaxf(v[i].w - tau, 0.0f);
                dst[i * 1000 + t] = o;
            }
        }

        if (r + 1 >= nloc) break;
        const long long gnext = grow + grid;

        // ---- 2) LDG tail of row r+1 (v[6],v[7] just freed by stores) -------
        if (t < 1000) {
            const float4* src = X4 + gnext * D4;
            v[6] = src[6000 + t];
            v[7] = src[7000 + t];
        }

        // ---- 3) wait TMA(r+1) on buffer (r+1)&1, copy 96KB with fused max --
        const int b = (r + 1) & 1;
        mbar_wait(smem_u32(&s_mbar[b]), (phbits >> b) & 1u);
        phbits ^= 1u << b;
        vmax = NINF;
        if (t < 1000) {
            const float4* b4 = reinterpret_cast<const float4*>(s_dyn + b * TMAF);
            #pragma unroll
            for (int i = 0; i < 6; i++) {
                float4 x = b4[i * 1000 + t];
                v[i] = x;
                vmax = fmaxf(vmax, fmaxf(fmaxf(x.x, x.y), fmaxf(x.z, x.w)));
            }
            vmax = fmaxf(vmax, fmaxf(fmaxf(v[6].x, v[6].y), fmaxf(v[6].z, v[6].w)));
            vmax = fmaxf(vmax, fmaxf(fmaxf(v[7].x, v[7].y), fmaxf(v[7].z, v[7].w)));
        }
        __syncthreads();                 // buffer b consumed by all warps

        // ---- 4) re-issue buffer b for row r+3 (row r+3 uses buffer b) ------
        if (t == 0 && r + 3 < nloc)
            tma_load(smem_u32(s_dyn + b * TMAF),
                     X + (gnext + 2LL * grid) * (long long)D, smem_u32(&s_mbar[b]));

        // ---- 5) solve tau(r+1); overlaps store drain + TMA(r+2) stream -----
        SOLVE_TAU();
    }
}

extern "C" void kernel_launch(void* const* d_in, const int* in_sizes, int n_in,
                              void* d_out, int out_size)
{
    const float* X = (const float*)d_in[0];
    float* Y = (float*)d_out;
    int rows = in_sizes[0] / D;                 // 4096

    int sms = 148;
    cudaDeviceGetAttribute(&sms, cudaDevAttrMultiProcessorCount, 0);
    int grid = (rows < sms) ? rows : sms;       // persistent: one CTA per SM

    size_t dyn = (size_t)(2 * TMAF + 32 * CSLOTS) * sizeof(float);  // 200192 B
    cudaFuncSetAttribute(sparsemax_kernel,
                         cudaFuncAttributeMaxDynamicSharedMemorySize, (int)dyn);
    sparsemax_kernel<<<grid, NTHREADS, dyn>>>(X, Y, rows);
}

// round 11
// speedup vs baseline: 1.2628x; 1.2628x over previous
#include <cuda_runtime.h>
#include <cstdint>

// Sparsemax along dim=-1 for X[4096, 32000] fp32. Persistent-CTA, R7 schedule
// (best known, 186.4us) with the lock-step tau-solve made cheap:
//  - compaction: per-thread candidate COUNT (predicated adds) + deterministic
//    block exclusive scan (1 warp shfl-scan + warp0 scan) + rare scattered
//    writes. Replaces 32 sequential ballot+popc+STS per thread (~0.8us/row).
//  - warp0 Newton holds the <=128 candidates in registers (no LDS per iter).
//  - one less block barrier: all warps redundantly reduce the 32 warp maxima.
// Schedule per iter (unchanged from R7): stores(r, tau known) -> wait TMA(r+1)
// -> copy+max -> issue TMA(r+2) -> solve tau(r+1).
// NO chunking / L2 prefetch / double-buffer / __stcs (all measured negative).

#define NTHREADS 1024
#define NVEC     8
#define D        32000
#define D4       8000
#define ROWB     (D * 4)       // 128000 bytes per row
#define CANDMAX  128           // candidates held in 4 regs/lane by warp0

__device__ __forceinline__ unsigned smem_u32(const void* p) {
    return (unsigned)__cvta_generic_to_shared(p);
}

__device__ __forceinline__ float warp_max_f(float v) {
    #pragma unroll
    for (int o = 16; o > 0; o >>= 1)
        v = fmaxf(v, __shfl_xor_sync(0xffffffffu, v, o));
    return v;
}

__device__ __forceinline__ void mbar_wait(unsigned mbar, unsigned ph) {
    asm volatile(
        "{\n\t"
        ".reg .pred P;\n\t"
        "WAIT_%=: \n\t"
        "mbarrier.try_wait.parity.acquire.cta.shared::cta.b64 P, [%0], %1, 0x989680;\n\t"
        "@P bra.uni DONE_%=;\n\t"
        "bra.uni WAIT_%=;\n\t"
        "DONE_%=: \n\t"
        "}\n\t" :: "r"(mbar), "r"(ph) : "memory");
}

__device__ __forceinline__ void tma_row(unsigned dst_smem, const float* src,
                                        unsigned mbar) {
    asm volatile("mbarrier.arrive.expect_tx.shared.b64 _, [%0], %1;"
                 :: "r"(mbar), "r"((unsigned)ROWB) : "memory");
    asm volatile("cp.async.bulk.shared::cluster.global.mbarrier::complete_tx::bytes "
                 "[%0], [%1], %2, [%3];"
                 :: "r"(dst_smem), "l"(src), "r"((unsigned)ROWB), "r"(mbar) : "memory");
}

__global__ void __launch_bounds__(NTHREADS, 1)
sparsemax_kernel(const float* __restrict__ X, float* __restrict__ Y, int nrows)
{
    __shared__ float s_warpf[32];
    __shared__ int   s_warpi[32];
    __shared__ int   s_total;
    __shared__ float s_bcast;
    __shared__ float s_tau;
    __shared__ float s_cand[CANDMAX];
    __shared__ __align__(8) unsigned long long s_mbar;

    extern __shared__ float s_dyn[];
    float* s_buf = s_dyn;            // 32000 floats = 128000 B TMA buffer

    const int t    = threadIdx.x;
    const int lane = t & 31;
    const int wid  = t >> 5;
    const int grid = gridDim.x;
    const unsigned mbar = smem_u32(&s_mbar);
    const float NINF = __int_as_float(0xff800000);

    if (t == 0)
        asm volatile("mbarrier.init.shared.b64 [%0], 1;" :: "r"(mbar) : "memory");
    __syncthreads();

    int row = blockIdx.x;
    if (row >= nrows) return;
    int next = row + grid;

    float4 v[NVEC];
    float vmax = NINF;
    float tau;

    // ---- prologue: LDG row0 (fused max); TMA row1 --------------------------
    {
        const float4* src = reinterpret_cast<const float4*>(X) + (long long)row * D4;
        #pragma unroll
        for (int i = 0; i < NVEC - 1; i++) {
            v[i] = src[t + i * NTHREADS];
            vmax = fmaxf(vmax, fmaxf(fmaxf(v[i].x, v[i].y), fmaxf(v[i].z, v[i].w)));
        }
        if (t + (NVEC - 1) * NTHREADS < D4) {
            v[NVEC - 1] = src[t + (NVEC - 1) * NTHREADS];
            vmax = fmaxf(vmax, fmaxf(fmaxf(v[NVEC-1].x, v[NVEC-1].y),
                                     fmaxf(v[NVEC-1].z, v[NVEC-1].w)));
        } else {
            v[NVEC - 1] = make_float4(NINF, NINF, NINF, NINF);
        }
    }
    if (t == 0 && next < nrows)
        tma_row(smem_u32(s_buf), X + (long long)next * D, mbar);
    unsigned ph = 0;

    // ================= cheap deterministic tau solve =========================
    #define SOLVE_TAU()                                                        \
    do {                                                                       \
        /* block max: warp reduce, share, all warps reduce the 32 maxima */    \
        float wm = warp_max_f(vmax);                                           \
        if (lane == 0) s_warpf[wid] = wm;                                      \
        __syncthreads();                                                       \
        const float tau0 = warp_max_f(s_warpf[lane]) - 1.0f;                   \
        /* per-thread candidate count (predicated adds, no ballots) */         \
        int cnt = 0;                                                           \
        _Pragma("unroll")                                                      \
        for (int i = 0; i < NVEC; i++)                                         \
            cnt += (v[i].x > tau0) + (v[i].y > tau0) +                         \
                   (v[i].z > tau0) + (v[i].w > tau0);                          \
        /* deterministic block exclusive scan of cnt */                        \
        int inc = cnt;                                                         \
        _Pragma("unroll")                                                      \
        for (int o = 1; o < 32; o <<= 1) {                                     \
            int y = __shfl_up_sync(0xffffffffu, inc, o);                       \
            if (lane >= o) inc += y;                                           \
        }                                                                      \
        if (lane == 31) s_warpi[wid] = inc;                                    \
        __syncthreads();                                                       \
        if (wid == 0) {                                                        \
            int wv = s_warpi[lane], wx = wv;                                   \
            _Pragma("unroll")                                                  \
            for (int o = 1; o < 32; o <<= 1) {                                 \
                int y = __shfl_up_sync(0xffffffffu, wx, o);                    \
                if (lane >= o) wx += y;                                        \
            }                                                                  \
            s_warpi[lane] = wx - wv;                                           \
            if (lane == 31) s_total = wx;                                      \
        }                                                                      \
        __syncthreads();                                                       \
        const int total = s_total;                                             \
        if (total <= CANDMAX) {                                                \
            if (cnt) {            /* ~31 threads block-wide take this */       \
                int off = s_warpi[wid] + (inc - cnt);                          \
                _Pragma("unroll")                                              \
                for (int i = 0; i < NVEC; i++) {                               \
                    if (v[i].x > tau0) s_cand[off++] = v[i].x;                 \
                    if (v[i].y > tau0) s_cand[off++] = v[i].y;                 \
                    if (v[i].z > tau0) s_cand[off++] = v[i].z;                 \
                    if (v[i].w > tau0) s_cand[off++] = v[i].w;                 \
                }                                                              \
            }                                                                  \
            __syncthreads();                                                   \
            if (wid == 0) {       /* Newton, candidates in registers */        \
                float c0 = (lane      < total) ? s_cand[lane]      : NINF;     \
                float c1 = (lane + 32 < total) ? s_cand[lane + 32] : NINF;     \
                float c2 = (lane + 64 < total) ? s_cand[lane + 64] : NINF;     \
                float c3 = (lane + 96 < total) ? s_cand[lane + 96] : NINF;     \
                float tt = tau0;                                               \
                for (int it = 0; it < 64; it++) {                              \
                    float s = 0.0f; int k = 0;                                 \
                    if (c0 > tt) { s += c0; k++; }                             \
                    if (c1 > tt) { s += c1; k++; }                             \
                    if (c2 > tt) { s += c2; k++; }                             \
                    if (c3 > tt) { s += c3; k++; }                             \
                    _Pragma("unroll")                                          \
                    for (int o = 16; o > 0; o >>= 1) {                         \
                        s += __shfl_xor_sync(0xffffffffu, s, o);               \
                        k += __shfl_xor_sync(0xffffffffu, k, o);               \
                    }                                                          \
                    float nt = (s - 1.0f) / (float)k;   /* k>=1 always */      \
                    if (nt == tt) break;                                       \
                    tt = nt;                                                   \
                }                                                              \
                if (lane == 0) s_tau = tt;                                     \
            }                                                                  \
            __syncthreads();                                                   \
            tau = s_tau;                                                       \
        } else {                                                               \
            /* fallback: block-wide Newton over registers (rare rows) */       \
            float tt = tau0;                                                   \
            for (int it = 0; it < 64; it++) {                                  \
                float s = 0.0f; int k = 0;                                     \
                _Pragma("unroll")                                              \
                for (int i = 0; i < NVEC; i++) {                               \
                    if (v[i].x > tt) { s += v[i].x; k++; }                     \
                    if (v[i].y > tt) { s += v[i].y; k++; }                     \
                    if (v[i].z > tt) { s += v[i].z; k++; }                     \
                    if (v[i].w > tt) { s += v[i].w; k++; }                     \
                }                                                              \
                _Pragma("unroll")                                              \
                for (int o = 16; o > 0; o >>= 1) {                             \
                    s += __shfl_xor_sync(0xffffffffu, s, o);                   \
                    k += __shfl_xor_sync(0xffffffffu, k, o);                   \
                }                                                              \
                if (lane == 0) { s_warpf[wid] = s; s_warpi[wid] = k; }         \
                __syncthreads();                                               \
                if (t == 0) {                                                  \
                    float S = 0.0f; int K = 0;                                 \
                    _Pragma("unroll")                                          \
                    for (int w = 0; w < 32; w++) { S += s_warpf[w]; K += s_warpi[w]; } \
                    s_bcast = (S - 1.0f) / (float)K;                           \
                }                                                              \
                __syncthreads();                                               \
                float nt = s_bcast;                                            \
                if (nt == tt) break;     /* uniform exit */                    \
                tt = nt;                                                       \
            }                                                                  \
            if (t == 0) s_tau = tt;                                            \
            __syncthreads();                                                   \
            tau = s_tau;                                                       \
        }                                                                      \
    } while (0)

    SOLVE_TAU();   // tau(row 0)

    for (;;) {
        // ---- 1) issue ALL stores for current row (tau precomputed, .wb) ----
        {
            float4* dst = reinterpret_cast<float4*>(Y) + (long long)row * D4;
            #pragma unroll
            for (int i = 0; i < NVEC; i++) {
                int idx = t + i * NTHREADS;
                if (i < NVEC - 1 || idx < D4) {
                    float4 o;
                    o.x = fmaxf(v[i].x - tau, 0.0f);
                    o.y = fmaxf(v[i].y - tau, 0.0f);
                    o.z = fmaxf(v[i].z - tau, 0.0f);
                    o.w = fmaxf(v[i].w - tau, 0.0f);
                    dst[idx] = o;
                }
            }
        }

        if (next >= nrows) break;

        // ---- 2) wait TMA(next), copy smem -> regs with fused max -----------
        mbar_wait(mbar, ph);
        ph ^= 1u;
        vmax = NINF;
        {
            const float4* sb4 = reinterpret_cast<const float4*>(s_buf);
            #pragma unroll
            for (int i = 0; i < NVEC - 1; i++) {
                v[i] = sb4[t + i * NTHREADS];
                vmax = fmaxf(vmax, fmaxf(fmaxf(v[i].x, v[i].y), fmaxf(v[i].z, v[i].w)));
            }
            if (t + (NVEC - 1) * NTHREADS < D4) {
                v[NVEC - 1] = sb4[t + (NVEC - 1) * NTHREADS];
                vmax = fmaxf(vmax, fmaxf(fmaxf(v[NVEC-1].x, v[NVEC-1].y),
                                         fmaxf(v[NVEC-1].z, v[NVEC-1].w)));
            }
            // tail lanes keep -inf padding from prologue
        }
        __syncthreads();            // buffer consumed by all warps

        // ---- 3) immediately re-issue TMA for row next+grid ------------------
        {
            int nn = next + grid;
            if (t == 0 && nn < nrows)
                tma_row(smem_u32(s_buf), X + (long long)nn * D, mbar);
            row = next;
            next = nn;
        }

        // ---- 4) solve tau for the new row (overlaps store drain + TMA) -----
        SOLVE_TAU();
    }
}

extern "C" void kernel_launch(void* const* d_in, const int* in_sizes, int n_in,
                              void* d_out, int out_size)
{
    const float* X = (const float*)d_in[0];
    float* Y = (float*)d_out;
    int rows = in_sizes[0] / D;                 // 4096

    int sms = 148;
    cudaDeviceGetAttribute(&sms, cudaDevAttrMultiProcessorCount, 0);
    int grid = (rows < sms) ? rows : sms;       // persistent: one CTA per SM

    size_t dyn = (size_t)D * sizeof(float);     // 128000 B
    cudaFuncSetAttribute(sparsemax_kernel,
                         cudaFuncAttributeMaxDynamicSharedMemorySize, (int)dyn);
    sparsemax_kernel<<<grid, NTHREADS, dyn>>>(X, Y, rows);
}

// round 12
// speedup vs baseline: 1.3295x; 1.0528x over previous
#include <cuda_runtime.h>
#include <cstdint>

// Sparsemax along dim=-1 for X[4096, 32000] fp32. Persistent-CTA, R7/R11
// schedule with stores and next-row copy FUSED into one interleaved loop:
//   iter r: wait TMA(r+1) [~0, issued a full iter ago] ->
//           { STG row r  |  LDS row r+1 + fused max }  interleaved ->
//           sync -> issue TMA(r+2) -> solve tau(r+1)
// Single 128KB TMA buffer, one sequential TMA in flight at a time (every
// multi-stream variant regressed: chunking x3, L2 prefetch x2, dbl-buffer x2).
// tau: support subset of {x > max-1}, count + block scan compaction (R11),
// warp0 Newton with candidates in registers; block-Newton fallback.

#define NTHREADS 1024
#define NVEC     8
#define D        32000
#define D4       8000
#define ROWB     (D * 4)       // 128000 bytes per row
#define CANDMAX  128           // candidates held in 4 regs/lane by warp0

__device__ __forceinline__ unsigned smem_u32(const void* p) {
    return (unsigned)__cvta_generic_to_shared(p);
}

__device__ __forceinline__ float warp_max_f(float v) {
    #pragma unroll
    for (int o = 16; o > 0; o >>= 1)
        v = fmaxf(v, __shfl_xor_sync(0xffffffffu, v, o));
    return v;
}

__device__ __forceinline__ void mbar_wait(unsigned mbar, unsigned ph) {
    asm volatile(
        "{\n\t"
        ".reg .pred P;\n\t"
        "WAIT_%=: \n\t"
        "mbarrier.try_wait.parity.acquire.cta.shared::cta.b64 P, [%0], %1, 0x989680;\n\t"
        "@P bra.uni DONE_%=;\n\t"
        "bra.uni WAIT_%=;\n\t"
        "DONE_%=: \n\t"
        "}\n\t" :: "r"(mbar), "r"(ph) : "memory");
}

__device__ __forceinline__ void tma_row(unsigned dst_smem, const float* src,
                                        unsigned mbar) {
    asm volatile("mbarrier.arrive.expect_tx.shared.b64 _, [%0], %1;"
                 :: "r"(mbar), "r"((unsigned)ROWB) : "memory");
    asm volatile("cp.async.bulk.shared::cluster.global.mbarrier::complete_tx::bytes "
                 "[%0], [%1], %2, [%3];"
                 :: "r"(dst_smem), "l"(src), "r"((unsigned)ROWB), "r"(mbar) : "memory");
}

__global__ void __launch_bounds__(NTHREADS, 1)
sparsemax_kernel(const float* __restrict__ X, float* __restrict__ Y, int nrows)
{
    __shared__ float s_warpf[32];
    __shared__ int   s_warpi[32];
    __shared__ int   s_total;
    __shared__ float s_bcast;
    __shared__ float s_tau;
    __shared__ float s_cand[CANDMAX];
    __shared__ __align__(8) unsigned long long s_mbar;

    extern __shared__ float s_dyn[];
    float* s_buf = s_dyn;            // 32000 floats = 128000 B TMA buffer

    const int t    = threadIdx.x;
    const int lane = t & 31;
    const int wid  = t >> 5;
    const int grid = gridDim.x;
    const unsigned mbar = smem_u32(&s_mbar);
    const float NINF = __int_as_float(0xff800000);

    if (t == 0)
        asm volatile("mbarrier.init.shared.b64 [%0], 1;" :: "r"(mbar) : "memory");
    __syncthreads();

    int row = blockIdx.x;
    if (row >= nrows) return;
    int next = row + grid;

    float4 v[NVEC];
    float vmax = NINF;
    float tau;

    // ---- prologue: LDG row0 (fused max); TMA row1 --------------------------
    {
        const float4* src = reinterpret_cast<const float4*>(X) + (long long)row * D4;
        #pragma unroll
        for (int i = 0; i < NVEC - 1; i++) {
            v[i] = src[t + i * NTHREADS];
            vmax = fmaxf(vmax, fmaxf(fmaxf(v[i].x, v[i].y), fmaxf(v[i].z, v[i].w)));
        }
        if (t + (NVEC - 1) * NTHREADS < D4) {
            v[NVEC - 1] = src[t + (NVEC - 1) * NTHREADS];
            vmax = fmaxf(vmax, fmaxf(fmaxf(v[NVEC-1].x, v[NVEC-1].y),
                                     fmaxf(v[NVEC-1].z, v[NVEC-1].w)));
        } else {
            v[NVEC - 1] = make_float4(NINF, NINF, NINF, NINF);
        }
    }
    if (t == 0 && next < nrows)
        tma_row(smem_u32(s_buf), X + (long long)next * D, mbar);
    unsigned ph = 0;

    // ================= cheap deterministic tau solve (R11) ===================
    #define SOLVE_TAU()                                                        \
    do {                                                                       \
        float wm = warp_max_f(vmax);                                           \
        if (lane == 0) s_warpf[wid] = wm;                                      \
        __syncthreads();                                                       \
        const float tau0 = warp_max_f(s_warpf[lane]) - 1.0f;                   \
        int cnt = 0;                                                           \
        _Pragma("unroll")                                                      \
        for (int i = 0; i < NVEC; i++)                                         \
            cnt += (v[i].x > tau0) + (v[i].y > tau0) +                         \
                   (v[i].z > tau0) + (v[i].w > tau0);                          \
        int inc = cnt;                                                         \
        _Pragma("unroll")                                                      \
        for (int o = 1; o < 32; o <<= 1) {                                     \
            int y = __shfl_up_sync(0xffffffffu, inc, o);                       \
            if (lane >= o) inc += y;                                           \
        }                                                                      \
        if (lane == 31) s_warpi[wid] = inc;                                    \
        __syncthreads();                                                       \
        if (wid == 0) {                                                        \
            int wv = s_warpi[lane], wx = wv;                                   \
            _Pragma("unroll")                                                  \
            for (int o = 1; o < 32; o <<= 1) {                                 \
                int y = __shfl_up_sync(0xffffffffu, wx, o);                    \
                if (lane >= o) wx += y;                                        \
            }                                                                  \
            s_warpi[lane] = wx - wv;                                           \
            if (lane == 31) s_total = wx;                                      \
        }                                                                      \
        __syncthreads();                                                       \
        const int total = s_total;                                             \
        if (total <= CANDMAX) {                                                \
            if (cnt) {                                                         \
                int off = s_warpi[wid] + (inc - cnt);                          \
                _Pragma("unroll")                                              \
                for (int i = 0; i < NVEC; i++) {                               \
                    if (v[i].x > tau0) s_cand[off++] = v[i].x;                 \
                    if (v[i].y > tau0) s_cand[off++] = v[i].y;                 \
                    if (v[i].z > tau0) s_cand[off++] = v[i].z;                 \
                    if (v[i].w > tau0) s_cand[off++] = v[i].w;                 \
                }                                                              \
            }                                                                  \
            __syncthreads();                                                   \
            if (wid == 0) {                                                    \
                float c0 = (lane      < total) ? s_cand[lane]      : NINF;     \
                float c1 = (lane + 32 < total) ? s_cand[lane + 32] : NINF;     \
                float c2 = (lane + 64 < total) ? s_cand[lane + 64] : NINF;     \
                float c3 = (lane + 96 < total) ? s_cand[lane + 96] : NINF;     \
                float tt = tau0;                                               \
                for (int it = 0; it < 64; it++) {                              \
                    float s = 0.0f; int k = 0;                                 \
                    if (c0 > tt) { s += c0; k++; }                             \
                    if (c1 > tt) { s += c1; k++; }                             \
                    if (c2 > tt) { s += c2; k++; }                             \
                    if (c3 > tt) { s += c3; k++; }                             \
                    _Pragma("unroll")                                          \
                    for (int o = 16; o > 0; o >>= 1) {                         \
                        s += __shfl_xor_sync(0xffffffffu, s, o);               \
                        k += __shfl_xor_sync(0xffffffffu, k, o);               \
                    }                                                          \
                    float nt = (s - 1.0f) / (float)k;                          \
                    if (nt == tt) break;                                       \
                    tt = nt;                                                   \
                }                                                              \
                if (lane == 0) s_tau = tt;                                     \
            }                                                                  \
            __syncthreads();                                                   \
            tau = s_tau;                                                       \
        } else {                                                               \
            float tt = tau0;                                                   \
            for (int it = 0; it < 64; it++) {                                  \
                float s = 0.0f; int k = 0;                                     \
                _Pragma("unroll")                                              \
                for (int i = 0; i < NVEC; i++) {                               \
                    if (v[i].x > tt) { s += v[i].x; k++; }                     \
                    if (v[i].y > tt) { s += v[i].y; k++; }                     \
                    if (v[i].z > tt) { s += v[i].z; k++; }                     \
                    if (v[i].w > tt) { s += v[i].w; k++; }                     \
                }                                                              \
                _Pragma("unroll")                                              \
                for (int o = 16; o > 0; o >>= 1) {                             \
                    s += __shfl_xor_sync(0xffffffffu, s, o);                   \
                    k += __shfl_xor_sync(0xffffffffu, k, o);                   \
                }                                                              \
                if (lane == 0) { s_warpf[wid] = s; s_warpi[wid] = k; }         \
                __syncthreads();                                               \
                if (t == 0) {                                                  \
                    float S = 0.0f; int K = 0;                                 \
                    _Pragma("unroll")                                          \
                    for (int w = 0; w < 32; w++) { S += s_warpf[w]; K += s_warpi[w]; } \
                    s_bcast = (S - 1.0f) / (float)K;                           \
                }                                                              \
                __syncthreads();                                               \
                float nt = s_bcast;                                            \
                if (nt == tt) break;                                           \
                tt = nt;                                                       \
            }                                                                  \
            if (t == 0) s_tau = tt;                                            \
            __syncthreads();                                                   \
            tau = s_tau;                                                       \
        }                                                                      \
    } while (0)

    SOLVE_TAU();   // tau(row 0)

    for (;;) {
        float4* dst = reinterpret_cast<float4*>(Y) + (long long)row * D4;

        if (next >= nrows) {
            // epilogue: stores only
            #pragma unroll
            for (int i = 0; i < NVEC; i++) {
                int idx = t + i * NTHREADS;
                if (i < NVEC - 1 || idx < D4) {
                    float4 o;
                    o.x = fmaxf(v[i].x - tau, 0.0f);
                    o.y = fmaxf(v[i].y - tau, 0.0f);
                    o.z = fmaxf(v[i].z - tau, 0.0f);
                    o.w = fmaxf(v[i].w - tau, 0.0f);
                    dst[idx] = o;
                }
            }
            break;
        }

        // ---- 1) wait TMA(next) (issued a full iteration ago; ~0 cost) ------
        mbar_wait(mbar, ph);
        ph ^= 1u;

        // ---- 2) fused: store row(r) | load row(r+1) from smem, fused max ---
        float vnew = NINF;
        {
            const float4* sb4 = reinterpret_cast<const float4*>(s_buf);
            #pragma unroll
            for (int i = 0; i < NVEC; i++) {
                int idx = t + i * NTHREADS;
                if (i < NVEC - 1 || idx < D4) {
                    float4 o;
                    o.x = fmaxf(v[i].x - tau, 0.0f);
                    o.y = fmaxf(v[i].y - tau, 0.0f);
                    o.z = fmaxf(v[i].z - tau, 0.0f);
                    o.w = fmaxf(v[i].w - tau, 0.0f);
                    float4 x = sb4[idx];          // LDS overlaps STG
                    dst[idx] = o;
                    v[i] = x;
                    vnew = fmaxf(vnew, fmaxf(fmaxf(x.x, x.y), fmaxf(x.z, x.w)));
                }
                // tail lanes keep -inf padding
            }
        }
        vmax = vnew;
        __syncthreads();            // buffer consumed by all warps

        // ---- 3) immediately re-issue TMA for row next+grid ------------------
        {
            int nn = next + grid;
            if (t == 0 && nn < nrows)
                tma_row(smem_u32(s_buf), X + (long long)nn * D, mbar);
            row = next;
            next = nn;
        }

        // ---- 4) solve tau for the new row (overlaps store drain + TMA) -----
        SOLVE_TAU();
    }
}

extern "C" void kernel_launch(void* const* d_in, const int* in_sizes, int n_in,
                              void* d_out, int out_size)
{
    const float* X = (const float*)d_in[0];
    float* Y = (float*)d_out;
    int rows = in_sizes[0] / D;                 // 4096

    int sms = 148;
    cudaDeviceGetAttribute(&sms, cudaDevAttrMultiProcessorCount, 0);
    int grid = (rows < sms) ? rows : sms;       // persistent: one CTA per SM

    size_t dyn = (size_t)D * sizeof(float);     // 128000 B
    cudaFuncSetAttribute(sparsemax_kernel,
                         cudaFuncAttributeMaxDynamicSharedMemorySize, (int)dyn);
    sparsemax_kernel<<<grid, NTHREADS, dyn>>>(X, Y, rows);
}

// round 13
// speedup vs baseline: 1.3545x; 1.0187x over previous
#include <cuda_runtime.h>
#include <cstdint>

// Sparsemax along dim=-1 for X[4096, 32000] fp32. Persistent-CTA, R12 fused
// schedule with a 3-sync tau solve:
//   iter r: wait TMA(r+1) -> { STG row r | LDS row r+1 + fused max } -> sync
//           -> issue TMA(r+2) -> solve tau(r+1)  [3 syncs, all-warp Newton]
// Solve: S1 block max; count + warp scan; S2 warp totals -> EVERY warp
// redundantly scans the 32 totals in registers (own base + grand total, no
// extra sync); scattered candidate writes; S3; then ALL warps run the
// identical register Newton -> tau computed locally, no broadcast sync.
// Single 128KB TMA buffer (multi-stream variants all regressed).

#define NTHREADS 1024
#define NVEC     8
#define D        32000
#define D4       8000
#define ROWB     (D * 4)       // 128000 bytes per row
#define CANDMAX  128           // candidates held in 4 regs/lane

__device__ __forceinline__ unsigned smem_u32(const void* p) {
    return (unsigned)__cvta_generic_to_shared(p);
}

__device__ __forceinline__ float warp_max_f(float v) {
    #pragma unroll
    for (int o = 16; o > 0; o >>= 1)
        v = fmaxf(v, __shfl_xor_sync(0xffffffffu, v, o));
    return v;
}

__device__ __forceinline__ void mbar_wait(unsigned mbar, unsigned ph) {
    asm volatile(
        "{\n\t"
        ".reg .pred P;\n\t"
        "WAIT_%=: \n\t"
        "mbarrier.try_wait.parity.acquire.cta.shared::cta.b64 P, [%0], %1, 0x989680;\n\t"
        "@P bra.uni DONE_%=;\n\t"
        "bra.uni WAIT_%=;\n\t"
        "DONE_%=: \n\t"
        "}\n\t" :: "r"(mbar), "r"(ph) : "memory");
}

__device__ __forceinline__ void tma_row(unsigned dst_smem, const float* src,
                                        unsigned mbar) {
    asm volatile("mbarrier.arrive.expect_tx.shared.b64 _, [%0], %1;"
                 :: "r"(mbar), "r"((unsigned)ROWB) : "memory");
    asm volatile("cp.async.bulk.shared::cluster.global.mbarrier::complete_tx::bytes "
                 "[%0], [%1], %2, [%3];"
                 :: "r"(dst_smem), "l"(src), "r"((unsigned)ROWB), "r"(mbar) : "memory");
}

__global__ void __launch_bounds__(NTHREADS, 1)
sparsemax_kernel(const float* __restrict__ X, float* __restrict__ Y, int nrows)
{
    __shared__ float s_warpf[32];
    __shared__ int   s_warpi[32];
    __shared__ float s_bcast;
    __shared__ float s_tau;
    __shared__ float s_cand[CANDMAX];
    __shared__ __align__(8) unsigned long long s_mbar;

    extern __shared__ float s_dyn[];
    float* s_buf = s_dyn;            // 32000 floats = 128000 B TMA buffer

    const int t    = threadIdx.x;
    const int lane = t & 31;
    const int wid  = t >> 5;
    const int grid = gridDim.x;
    const unsigned mbar = smem_u32(&s_mbar);
    const float NINF = __int_as_float(0xff800000);

    if (t == 0)
        asm volatile("mbarrier.init.shared.b64 [%0], 1;" :: "r"(mbar) : "memory");
    __syncthreads();

    int row = blockIdx.x;
    if (row >= nrows) return;
    int next = row + grid;

    float4 v[NVEC];
    float vmax = NINF;
    float tau;

    // ---- prologue: LDG row0 (fused max); TMA row1 --------------------------
    {
        const float4* src = reinterpret_cast<const float4*>(X) + (long long)row * D4;
        #pragma unroll
        for (int i = 0; i < NVEC - 1; i++) {
            v[i] = src[t + i * NTHREADS];
            vmax = fmaxf(vmax, fmaxf(fmaxf(v[i].x, v[i].y), fmaxf(v[i].z, v[i].w)));
        }
        if (t + (NVEC - 1) * NTHREADS < D4) {
            v[NVEC - 1] = src[t + (NVEC - 1) * NTHREADS];
            vmax = fmaxf(vmax, fmaxf(fmaxf(v[NVEC-1].x, v[NVEC-1].y),
                                     fmaxf(v[NVEC-1].z, v[NVEC-1].w)));
        } else {
            v[NVEC - 1] = make_float4(NINF, NINF, NINF, NINF);
        }
    }
    if (t == 0 && next < nrows)
        tma_row(smem_u32(s_buf), X + (long long)next * D, mbar);
    unsigned ph = 0;

    // ================= 3-sync deterministic tau solve ========================
    #define SOLVE_TAU()                                                        \
    do {                                                                       \
        /* S1: block max */                                                    \
        float wm = warp_max_f(vmax);                                           \
        if (lane == 0) s_warpf[wid] = wm;                                      \
        __syncthreads();                                      /* S1 */         \
        const float tau0 = warp_max_f(s_warpf[lane]) - 1.0f;                   \
        /* per-thread candidate count + intra-warp inclusive scan */           \
        int cnt = 0;                                                           \
        _Pragma("unroll")                                                      \
        for (int i = 0; i < NVEC; i++)                                         \
            cnt += (v[i].x > tau0) + (v[i].y > tau0) +                         \
                   (v[i].z > tau0) + (v[i].w > tau0);                          \
        int inc = cnt;                                                         \
        _Pragma("unroll")                                                      \
        for (int o = 1; o < 32; o <<= 1) {                                     \
            int y = __shfl_up_sync(0xffffffffu, inc, o);                       \
            if (lane >= o) inc += y;                                           \
        }                                                                      \
        if (lane == 31) s_warpi[wid] = inc;                                    \
        __syncthreads();                                      /* S2 */         \
        /* every warp: redundant cross-warp scan in registers */               \
        int wt = s_warpi[lane];                                                \
        int wx = wt;                                                           \
        _Pragma("unroll")                                                      \
        for (int o = 1; o < 32; o <<= 1) {                                     \
            int y = __shfl_up_sync(0xffffffffu, wx, o);                        \
            if (lane >= o) wx += y;                                            \
        }                                                                      \
        const int total  = __shfl_sync(0xffffffffu, wx, 31);                   \
        const int mybase = __shfl_sync(0xffffffffu, wx - wt, wid);             \
        if (total <= CANDMAX) {                                                \
            if (cnt) {                  /* ~31 threads block-wide */           \
                int off = mybase + (inc - cnt);                                \
                _Pragma("unroll")                                              \
                for (int i = 0; i < NVEC; i++) {                               \
                    if (v[i].x > tau0) s_cand[off++] = v[i].x;                 \
                    if (v[i].y > tau0) s_cand[off++] = v[i].y;                 \
                    if (v[i].z > tau0) s_cand[off++] = v[i].z;                 \
                    if (v[i].w > tau0) s_cand[off++] = v[i].w;                 \
                }                                                              \
            }                                                                  \
            __syncthreads();                                  /* S3 */         \
            /* ALL warps run identical register Newton -> same tau bits */     \
            float c0 = (lane      < total) ? s_cand[lane]      : NINF;         \
            float c1 = (lane + 32 < total) ? s_cand[lane + 32] : NINF;         \
            float c2 = (lane + 64 < total) ? s_cand[lane + 64] : NINF;         \
            float c3 = (lane + 96 < total) ? s_cand[lane + 96] : NINF;         \
            float tt = tau0;                                                   \
            for (int it = 0; it < 64; it++) {                                  \
                float s = 0.0f; int k = 0;                                     \
                if (c0 > tt) { s += c0; k++; }                                 \
                if (c1 > tt) { s += c1; k++; }                                 \
                if (c2 > tt) { s += c2; k++; }                                 \
                if (c3 > tt) { s += c3; k++; }                                 \
                _Pragma("unroll")                                              \
                for (int o = 16; o > 0; o >>= 1) {                             \
                    s += __shfl_xor_sync(0xffffffffu, s, o);                   \
                    k += __shfl_xor_sync(0xffffffffu, k, o);                   \
                }                                                              \
                float nt = (s - 1.0f) / (float)k;     /* k>=1 always */        \
                if (nt == tt) break;                                           \
                tt = nt;                                                       \
            }                                                                  \
            tau = tt;                   /* no broadcast sync needed */         \
        } else {                                                               \
            /* fallback: block-wide Newton over registers (rare rows) */       \
            float tt = tau0;                                                   \
            for (int it = 0; it < 64; it++) {                                  \
                float s = 0.0f; int k = 0;                                     \
                _Pragma("unroll")                                              \
                for (int i = 0; i < NVEC; i++) {                               \
                    if (v[i].x > tt) { s += v[i].x; k++; }                     \
                    if (v[i].y > tt) { s += v[i].y; k++; }                     \
                    if (v[i].z > tt) { s += v[i].z; k++; }                     \
                    if (v[i].w > tt) { s += v[i].w; k++; }                     \
                }                                                              \
                _Pragma("unroll")                                              \
                for (int o = 16; o > 0; o >>= 1) {                             \
                    s += __shfl_xor_sync(0xffffffffu, s, o);                   \
                    k += __shfl_xor_sync(0xffffffffu, k, o);                   \
                }                                                              \
                if (lane == 0) { s_warpf[wid] = s; s_warpi[wid] = k; }         \
                __syncthreads();                                               \
                if (t == 0) {                                                  \
                    float S = 0.0f; int K = 0;                                 \
                    _Pragma("unroll")                                          \
                    for (int w = 0; w < 32; w++) { S += s_warpf[w]; K += s_warpi[w]; } \
                    s_bcast = (S - 1.0f) / (float)K;                           \
                }                                                              \
                __syncthreads();                                               \
                float nt = s_bcast;                                            \
                if (nt == tt) break;     /* uniform exit */                    \
                tt = nt;                                                       \
            }                                                                  \
            if (t == 0) s_tau = tt;                                            \
            __syncthreads();                                                   \
            tau = s_tau;                                                       \
        }                                                                      \
    } while (0)

    SOLVE_TAU();   // tau(row 0)

    for (;;) {
        float4* dst = reinterpret_cast<float4*>(Y) + (long long)row * D4;

        if (next >= nrows) {
            // epilogue: stores only
            #pragma unroll
            for (int i = 0; i < NVEC; i++) {
                int idx = t + i * NTHREADS;
                if (i < NVEC - 1 || idx < D4) {
                    float4 o;
                    o.x = fmaxf(v[i].x - tau, 0.0f);
                    o.y = fmaxf(v[i].y - tau, 0.0f);
                    o.z = fmaxf(v[i].z - tau, 0.0f);
                    o.w = fmaxf(v[i].w - tau, 0.0f);
                    dst[idx] = o;
                }
            }
            break;
        }

        // ---- 1) wait TMA(next) (issued a full iteration ago) ---------------
        mbar_wait(mbar, ph);
        ph ^= 1u;

        // ---- 2) fused: store row(r) | load row(r+1) from smem, fused max ---
        float vnew = NINF;
        {
            const float4* sb4 = reinterpret_cast<const float4*>(s_buf);
            #pragma unroll
            for (int i = 0; i < NVEC; i++) {
                int idx = t + i * NTHREADS;
                if (i < NVEC - 1 || idx < D4) {
                    float4 o;
                    o.x = fmaxf(v[i].x - tau, 0.0f);
                    o.y = fmaxf(v[i].y - tau, 0.0f);
                    o.z = fmaxf(v[i].z - tau, 0.0f);
                    o.w = fmaxf(v[i].w - tau, 0.0f);
                    float4 x = sb4[idx];          // LDS overlaps STG
                    dst[idx] = o;
                    v[i] = x;
                    vnew = fmaxf(vnew, fmaxf(fmaxf(x.x, x.y), fmaxf(x.z, x.w)));
                }
                // tail lanes keep -inf padding
            }
        }
        vmax = vnew;
        __syncthreads();            // buffer consumed by all warps

        // ---- 3) immediately re-issue TMA for row next+grid ------------------
        {
            int nn = next + grid;
            if (t == 0 && nn < nrows)
                tma_row(smem_u32(s_buf), X + (long long)nn * D, mbar);
            row = next;
            next = nn;
        }

        // ---- 4) solve tau for the new row (overlaps store drain + TMA) -----
        SOLVE_TAU();
    }
}

extern "C" void kernel_launch(void* const* d_in, const int* in_sizes, int n_in,
                              void* d_out, int out_size)
{
    const float* X = (const float*)d_in[0];
    float* Y = (float*)d_out;
    int rows = in_sizes[0] / D;                 // 4096

    int sms = 148;
    cudaDeviceGetAttribute(&sms, cudaDevAttrMultiProcessorCount, 0);
    int grid = (rows < sms) ? rows : sms;       // persistent: one CTA per SM

    size_t dyn = (size_t)D * sizeof(float);     // 128000 B
    cudaFuncSetAttribute(sparsemax_kernel,
                         cudaFuncAttributeMaxDynamicSharedMemorySize, (int)dyn);
    sparsemax_kernel<<<grid, NTHREADS, dyn>>>(X, Y, rows);
}